// round 1
// baseline (speedup 1.0000x reference)
#include <cuda_runtime.h>
#include <math.h>

#define B_ 4
#define T_ 2048
#define DM_ 2048
#define H_ 16
#define KV_ 8
#define HD_ 128
#define G_ 2

// Scratch (no allocations allowed) — static device globals.
__device__ float g_q[B_*T_*H_*HD_];   // 64 MB
__device__ float g_k[B_*T_*KV_*HD_];  // 32 MB
__device__ float g_v[B_*T_*KV_*HD_];  // 32 MB
__device__ float g_o[B_*T_*H_*HD_];   // 64 MB

// ---------------------------------------------------------------------------
// Generic fp32 GEMM: C[M,N] = A[M,K] * W[K,N].  BM=BN=128, BK=16, 256 thr,
// 8x8 register blocking. M%128==0, N%128==0, K%16==0 assumed (true here).
// ---------------------------------------------------------------------------
__global__ __launch_bounds__(256, 2)
void gemm128(const float* __restrict__ A, const float* __restrict__ W,
             float* __restrict__ C, int M, int N, int K)
{
    __shared__ float As[16][128];   // transposed: As[k][m]
    __shared__ float Bs[16][128];   // Bs[k][n]
    int tid = threadIdx.x;
    int ty = tid >> 4, tx = tid & 15;
    int bm = blockIdx.y * 128, bn = blockIdx.x * 128;
    float acc[8][8] = {};
    int arow = tid >> 2, acol = (tid & 3) << 2;
    int brow = tid >> 5, bcol = (tid & 31) << 2;

    for (int k0 = 0; k0 < K; k0 += 16) {
        #pragma unroll
        for (int p = 0; p < 2; p++) {
            int r = arow + p * 64;
            float4 a = *(const float4*)&A[(bm + r) * K + k0 + acol];
            As[acol + 0][r] = a.x; As[acol + 1][r] = a.y;
            As[acol + 2][r] = a.z; As[acol + 3][r] = a.w;
        }
        #pragma unroll
        for (int p = 0; p < 2; p++) {
            int r = brow + p * 8;
            *(float4*)&Bs[r][bcol] = *(const float4*)&W[(k0 + r) * N + bn + bcol];
        }
        __syncthreads();
        #pragma unroll
        for (int kk = 0; kk < 16; kk++) {
            float4 a0 = *(float4*)&As[kk][ty * 8];
            float4 a1 = *(float4*)&As[kk][ty * 8 + 4];
            float4 b0 = *(float4*)&Bs[kk][tx * 8];
            float4 b1 = *(float4*)&Bs[kk][tx * 8 + 4];
            float av[8] = {a0.x, a0.y, a0.z, a0.w, a1.x, a1.y, a1.z, a1.w};
            float bv[8] = {b0.x, b0.y, b0.z, b0.w, b1.x, b1.y, b1.z, b1.w};
            #pragma unroll
            for (int i = 0; i < 8; i++)
                #pragma unroll
                for (int j = 0; j < 8; j++)
                    acc[i][j] += av[i] * bv[j];
        }
        __syncthreads();
    }
    #pragma unroll
    for (int i = 0; i < 8; i++) {
        float* cp = &C[(bm + ty * 8 + i) * N + bn + tx * 8];
        *(float4*)cp       = make_float4(acc[i][0], acc[i][1], acc[i][2], acc[i][3]);
        *(float4*)(cp + 4) = make_float4(acc[i][4], acc[i][5], acc[i][6], acc[i][7]);
    }
}

// ---------------------------------------------------------------------------
// Fused RMSNorm + interleaved RoPE (+ optional output scale, used to fold the
// 1/sqrt(HD) softmax scale into q). One warp per (b,t,head) vector of HD=128.
// ---------------------------------------------------------------------------
__global__ void rmsrope(float* __restrict__ buf, const float* __restrict__ gamma,
                        const float* __restrict__ cosT, const float* __restrict__ sinT,
                        int nheads, float outscale)
{
    int gid  = blockIdx.x * blockDim.x + threadIdx.x;
    int lane = gid & 31;
    int w    = gid >> 5;                 // (b*T + t)*nheads + h
    int t    = (w / nheads) % T_;
    float* p = buf + (size_t)w * HD_ + lane * 4;
    float4 v = *(float4*)p;
    float ss = v.x * v.x + v.y * v.y + v.z * v.z + v.w * v.w;
    #pragma unroll
    for (int off = 16; off; off >>= 1) ss += __shfl_xor_sync(0xffffffffu, ss, off);
    float r = rsqrtf(ss * (1.0f / HD_) + 1e-6f);
    float4 g = *(const float4*)&gamma[lane * 4];
    float hx = v.x * r * g.x, hy = v.y * r * g.y;
    float hz = v.z * r * g.z, hw = v.w * r * g.w;
    int ci = t * HD_ + lane * 4;
    float c0 = cosT[ci], s0 = sinT[ci], c1 = cosT[ci + 2], s1 = sinT[ci + 2];
    float4 o;
    o.x = (hx * c0 - hy * s0) * outscale;
    o.y = (hy * c0 + hx * s0) * outscale;
    o.z = (hz * c1 - hw * s1) * outscale;
    o.w = (hw * c1 + hz * s1) * outscale;
    *(float4*)p = o;
}

// ---------------------------------------------------------------------------
// Flash attention (non-causal), 64 q-rows x 64 k-cols per iteration.
// smem tiles XOR-swizzled at float4 granularity: element (row, d4) stored at
// float4 index row*32 + (d4 ^ (row>>2))  → conflict-light reads in both the
// S (q·k) and PV stages. 80 KB dynamic smem, 256 threads, 2 CTAs/SM.
// ---------------------------------------------------------------------------
__global__ __launch_bounds__(256, 2)
void attn64(const float* __restrict__ q, const float* __restrict__ k,
            const float* __restrict__ v, float* __restrict__ o)
{
    extern __shared__ float4 sm4[];
    float4* qs  = sm4;          // 2048 float4 (64 x 128 f32)
    float4* kvs = sm4 + 2048;   // 2048 float4 (k tile, then v tile)
    float*  ps  = (float*)(sm4 + 4096); // 64 x 64 f32

    int b = blockIdx.z, h = blockIdx.y;
    int kvh = h / G_;
    int t0 = blockIdx.x * 64;
    int tid = threadIdx.x;
    int ty = tid >> 4, tx = tid & 15;

    #pragma unroll
    for (int p = 0; p < 8; p++) {
        int idx = tid + p * 256;
        int row = idx >> 5, d4 = idx & 31;
        qs[row * 32 + (d4 ^ (row >> 2))] =
            *(const float4*)&q[(((b * T_ + t0 + row) * H_ + h) << 7) + d4 * 4];
    }

    float m[4], l[4], acc[4][8];
    #pragma unroll
    for (int i = 0; i < 4; i++) {
        m[i] = -1e30f; l[i] = 0.f;
        #pragma unroll
        for (int j = 0; j < 8; j++) acc[i][j] = 0.f;
    }

    for (int kt = 0; kt < T_ / 64; kt++) {
        __syncthreads();   // previous PV done reading kvs
        #pragma unroll
        for (int p = 0; p < 8; p++) {
            int idx = tid + p * 256;
            int row = idx >> 5, d4 = idx & 31;
            kvs[row * 32 + (d4 ^ (row >> 2))] =
                *(const float4*)&k[(((b * T_ + kt * 64 + row) * KV_ + kvh) << 7) + d4 * 4];
        }
        __syncthreads();

        // S = q @ k^T  (q already carries 1/sqrt(HD))
        float s[4][4] = {};
        #pragma unroll 4
        for (int d4 = 0; d4 < 32; d4++) {
            float4 qv[4], kv[4];
            #pragma unroll
            for (int i = 0; i < 4; i++) qv[i] = qs[(ty * 4 + i) * 32 + (d4 ^ ty)];
            #pragma unroll
            for (int j = 0; j < 4; j++) kv[j] = kvs[(tx * 4 + j) * 32 + (d4 ^ tx)];
            #pragma unroll
            for (int i = 0; i < 4; i++)
                #pragma unroll
                for (int j = 0; j < 4; j++)
                    s[i][j] += qv[i].x * kv[j].x + qv[i].y * kv[j].y
                             + qv[i].z * kv[j].z + qv[i].w * kv[j].w;
        }

        // Online softmax over the 64-wide tile (rows split across 16 lanes).
        #pragma unroll
        for (int i = 0; i < 4; i++) {
            float rm = fmaxf(fmaxf(s[i][0], s[i][1]), fmaxf(s[i][2], s[i][3]));
            #pragma unroll
            for (int off = 8; off; off >>= 1)
                rm = fmaxf(rm, __shfl_xor_sync(0xffffffffu, rm, off, 16));
            float nm = fmaxf(m[i], rm);
            float pj[4], rs = 0.f;
            #pragma unroll
            for (int j = 0; j < 4; j++) { pj[j] = __expf(s[i][j] - nm); rs += pj[j]; }
            #pragma unroll
            for (int off = 8; off; off >>= 1)
                rs += __shfl_xor_sync(0xffffffffu, rs, off, 16);
            float corr = __expf(m[i] - nm);
            l[i] = l[i] * corr + rs;
            m[i] = nm;
            #pragma unroll
            for (int j = 0; j < 8; j++) acc[i][j] *= corr;
            *(float4*)&ps[(ty * 4 + i) * 64 + tx * 4] = make_float4(pj[0], pj[1], pj[2], pj[3]);
        }
        __syncthreads();   // done reading kvs(k), ps written

        #pragma unroll
        for (int p = 0; p < 8; p++) {
            int idx = tid + p * 256;
            int row = idx >> 5, d4 = idx & 31;
            kvs[row * 32 + (d4 ^ (row >> 2))] =
                *(const float4*)&v[(((b * T_ + kt * 64 + row) * KV_ + kvh) << 7) + d4 * 4];
        }
        __syncthreads();

        // O += P @ V
        #pragma unroll 2
        for (int kk = 0; kk < 64; kk++) {
            float4 va = kvs[kk * 32 + ((tx * 2)     ^ (kk >> 2))];
            float4 vb = kvs[kk * 32 + ((tx * 2 + 1) ^ (kk >> 2))];
            #pragma unroll
            for (int i = 0; i < 4; i++) {
                float pv = ps[(ty * 4 + i) * 64 + kk];
                acc[i][0] += pv * va.x; acc[i][1] += pv * va.y;
                acc[i][2] += pv * va.z; acc[i][3] += pv * va.w;
                acc[i][4] += pv * vb.x; acc[i][5] += pv * vb.y;
                acc[i][6] += pv * vb.z; acc[i][7] += pv * vb.w;
            }
        }
    }

    #pragma unroll
    for (int i = 0; i < 4; i++) {
        float inv = 1.0f / l[i];
        float* op = &o[(((b * T_ + t0 + ty * 4 + i) * H_ + h) << 7) + tx * 8];
        *(float4*)op       = make_float4(acc[i][0] * inv, acc[i][1] * inv,
                                         acc[i][2] * inv, acc[i][3] * inv);
        *(float4*)(op + 4) = make_float4(acc[i][4] * inv, acc[i][5] * inv,
                                         acc[i][6] * inv, acc[i][7] * inv);
    }
}

// ---------------------------------------------------------------------------
// Launch: QKV GEMMs -> RMSNorm+RoPE (q gets softmax scale) -> flash attn -> Wo
// ---------------------------------------------------------------------------
extern "C" void kernel_launch(void* const* d_in, const int* in_sizes, int n_in,
                              void* d_out, int out_size)
{
    const float* x    = (const float*)d_in[0];
    const float* cosT = (const float*)d_in[1];
    const float* sinT = (const float*)d_in[2];
    const float* Wq   = (const float*)d_in[3];
    const float* Wk   = (const float*)d_in[4];
    const float* Wv   = (const float*)d_in[5];
    const float* Wo   = (const float*)d_in[6];
    const float* qg   = (const float*)d_in[7];
    const float* kg   = (const float*)d_in[8];

    float *q, *k, *v, *o;
    cudaGetSymbolAddress((void**)&q, g_q);
    cudaGetSymbolAddress((void**)&k, g_k);
    cudaGetSymbolAddress((void**)&v, g_v);
    cudaGetSymbolAddress((void**)&o, g_o);

    const int M = B_ * T_;  // 8192

    gemm128<<<dim3((H_ * HD_) / 128, M / 128), 256>>>(x, Wq, q, M, H_ * HD_, DM_);
    gemm128<<<dim3((KV_ * HD_) / 128, M / 128), 256>>>(x, Wk, k, M, KV_ * HD_, DM_);
    gemm128<<<dim3((KV_ * HD_) / 128, M / 128), 256>>>(x, Wv, v, M, KV_ * HD_, DM_);

    rmsrope<<<(M * H_) / 8, 256>>>(q, qg, cosT, sinT, H_, 0.0883883476483184405f);
    rmsrope<<<(M * KV_) / 8, 256>>>(k, kg, cosT, sinT, KV_, 1.0f);

    cudaFuncSetAttribute(attn64, cudaFuncAttributeMaxDynamicSharedMemorySize, 81920);
    attn64<<<dim3(T_ / 64, H_, B_), 256, 81920>>>(q, k, v, o);

    gemm128<<<dim3(DM_ / 128, M / 128), 256>>>(o, Wo, (float*)d_out, M, DM_, DM_);
}

// round 2
// speedup vs baseline: 1.0024x; 1.0024x over previous
#include <cuda_runtime.h>
#include <math.h>
#include <stdint.h>

#define B_ 4
#define T_ 2048
#define DM_ 2048
#define H_ 16
#define KV_ 8
#define HD_ 128
#define G_ 2

// Scratch (no allocations allowed) — static device globals.
__device__ float g_q[B_*T_*H_*HD_];   // 64 MB
__device__ float g_k[B_*T_*KV_*HD_];  // 32 MB
__device__ float g_v[B_*T_*KV_*HD_];  // 32 MB
__device__ float g_o[B_*T_*H_*HD_];   // 64 MB

// ---------------------------------------------------------------------------
// TF32 helpers
// ---------------------------------------------------------------------------
__device__ __forceinline__ uint32_t f2tf32(float f) {
    uint32_t r;
    asm("cvt.rna.tf32.f32 %0, %1;" : "=r"(r) : "f"(f));
    return r;
}

__device__ __forceinline__ void mma_tf32(float c[4],
                                         uint32_t a0, uint32_t a1, uint32_t a2, uint32_t a3,
                                         uint32_t b0, uint32_t b1) {
    asm volatile(
        "mma.sync.aligned.m16n8k8.row.col.f32.tf32.tf32.f32 "
        "{%0,%1,%2,%3}, {%4,%5,%6,%7}, {%8,%9}, {%0,%1,%2,%3};"
        : "+f"(c[0]), "+f"(c[1]), "+f"(c[2]), "+f"(c[3])
        : "r"(a0), "r"(a1), "r"(a2), "r"(a3), "r"(b0), "r"(b1));
}

// ---------------------------------------------------------------------------
// TF32 tensor-core GEMM: C[M,N] = A[M,K] * W[K,N].
// Block tile 128x128, BK=32, 256 threads = 8 warps in 2(m) x 4(n) grid,
// warp tile 64x32 (4 m-frags x 4 n-frags of m16n8k8).
// Smem padded for conflict-free fragment loads:
//   As[m][k] stride 36 (==4 mod 32): frag banks 4*(lane/4)+(lane%4) distinct.
//   Bs[k][n] stride 136 (==8 mod 32): frag banks 8*(lane%4)+(lane/4) distinct.
// ---------------------------------------------------------------------------
#define AS_STRIDE 36
#define BS_STRIDE 136

__global__ __launch_bounds__(256, 2)
void gemm_tf32(const float* __restrict__ A, const float* __restrict__ W,
               float* __restrict__ C, int M, int N, int K)
{
    __shared__ uint32_t As[128 * AS_STRIDE];
    __shared__ uint32_t Bs[32 * BS_STRIDE];

    int tid  = threadIdx.x;
    int lane = tid & 31;
    int warp = tid >> 5;
    int wm = (warp & 1) * 64;     // warp m-offset within block
    int wn = (warp >> 1) * 32;    // warp n-offset within block
    int bm = blockIdx.y * 128, bn = blockIdx.x * 128;

    float acc[4][4][4] = {};      // [fm][fn][reg]

    for (int k0 = 0; k0 < K; k0 += 32) {
        // Stage A tile (128 x 32) as tf32
        #pragma unroll
        for (int p = 0; p < 4; p++) {
            int idx = tid + p * 256;
            int m = idx >> 3, kk = (idx & 7) << 2;
            float4 a = *(const float4*)&A[(size_t)(bm + m) * K + k0 + kk];
            uint32_t* dst = &As[m * AS_STRIDE + kk];
            dst[0] = f2tf32(a.x); dst[1] = f2tf32(a.y);
            dst[2] = f2tf32(a.z); dst[3] = f2tf32(a.w);
        }
        // Stage B tile (32 x 128) as tf32
        #pragma unroll
        for (int p = 0; p < 4; p++) {
            int idx = tid + p * 256;
            int kk = idx >> 5, n = (idx & 31) << 2;
            float4 b = *(const float4*)&W[(size_t)(k0 + kk) * N + bn + n];
            uint32_t* dst = &Bs[kk * BS_STRIDE + n];
            dst[0] = f2tf32(b.x); dst[1] = f2tf32(b.y);
            dst[2] = f2tf32(b.z); dst[3] = f2tf32(b.w);
        }
        __syncthreads();

        #pragma unroll
        for (int ks = 0; ks < 4; ks++) {
            int kc = ks * 8 + (lane & 3);
            // A fragments: 4 m-frags x 4 regs
            uint32_t af[4][4];
            #pragma unroll
            for (int fm = 0; fm < 4; fm++) {
                int r = wm + fm * 16 + (lane >> 2);
                af[fm][0] = As[r * AS_STRIDE + kc];
                af[fm][1] = As[(r + 8) * AS_STRIDE + kc];
                af[fm][2] = As[r * AS_STRIDE + kc + 4];
                af[fm][3] = As[(r + 8) * AS_STRIDE + kc + 4];
            }
            #pragma unroll
            for (int fn = 0; fn < 4; fn++) {
                int n = wn + fn * 8 + (lane >> 2);
                uint32_t b0 = Bs[kc * BS_STRIDE + n];
                uint32_t b1 = Bs[(kc + 4) * BS_STRIDE + n];
                #pragma unroll
                for (int fm = 0; fm < 4; fm++)
                    mma_tf32(acc[fm][fn], af[fm][0], af[fm][1], af[fm][2], af[fm][3], b0, b1);
            }
        }
        __syncthreads();
    }

    // Store C: per (fm,fn) thread owns (r, c),(r, c+1),(r+8, c),(r+8, c+1)
    #pragma unroll
    for (int fm = 0; fm < 4; fm++) {
        #pragma unroll
        for (int fn = 0; fn < 4; fn++) {
            int r = bm + wm + fm * 16 + (lane >> 2);
            int c = bn + wn + fn * 8 + (lane & 3) * 2;
            *(float2*)&C[(size_t)r * N + c]       = make_float2(acc[fm][fn][0], acc[fm][fn][1]);
            *(float2*)&C[(size_t)(r + 8) * N + c] = make_float2(acc[fm][fn][2], acc[fm][fn][3]);
        }
    }
}

// ---------------------------------------------------------------------------
// Fused RMSNorm + interleaved RoPE (+ optional output scale: 1/sqrt(HD) is
// folded into q). One warp per (b,t,head) vector of HD=128.
// ---------------------------------------------------------------------------
__global__ void rmsrope(float* __restrict__ buf, const float* __restrict__ gamma,
                        const float* __restrict__ cosT, const float* __restrict__ sinT,
                        int nheads, float outscale)
{
    int gid  = blockIdx.x * blockDim.x + threadIdx.x;
    int lane = gid & 31;
    int w    = gid >> 5;                 // (b*T + t)*nheads + h
    int t    = (w / nheads) % T_;
    float* p = buf + (size_t)w * HD_ + lane * 4;
    float4 v = *(float4*)p;
    float ss = v.x * v.x + v.y * v.y + v.z * v.z + v.w * v.w;
    #pragma unroll
    for (int off = 16; off; off >>= 1) ss += __shfl_xor_sync(0xffffffffu, ss, off);
    float r = rsqrtf(ss * (1.0f / HD_) + 1e-6f);
    float4 g = *(const float4*)&gamma[lane * 4];
    float hx = v.x * r * g.x, hy = v.y * r * g.y;
    float hz = v.z * r * g.z, hw = v.w * r * g.w;
    int ci = t * HD_ + lane * 4;
    float c0 = cosT[ci], s0 = sinT[ci], c1 = cosT[ci + 2], s1 = sinT[ci + 2];
    float4 o;
    o.x = (hx * c0 - hy * s0) * outscale;
    o.y = (hy * c0 + hx * s0) * outscale;
    o.z = (hz * c1 - hw * s1) * outscale;
    o.w = (hw * c1 + hz * s1) * outscale;
    *(float4*)p = o;
}

// ---------------------------------------------------------------------------
// Flash attention (non-causal), 64 q-rows x 64 k-cols per iteration.
// fp32 SIMT with XOR-swizzled smem. 80 KB dynamic smem, 256 threads.
// ---------------------------------------------------------------------------
__global__ __launch_bounds__(256, 2)
void attn64(const float* __restrict__ q, const float* __restrict__ k,
            const float* __restrict__ v, float* __restrict__ o)
{
    extern __shared__ float4 sm4[];
    float4* qs  = sm4;          // 2048 float4 (64 x 128 f32)
    float4* kvs = sm4 + 2048;   // 2048 float4 (k tile, then v tile)
    float*  ps  = (float*)(sm4 + 4096); // 64 x 64 f32

    int b = blockIdx.z, h = blockIdx.y;
    int kvh = h / G_;
    int t0 = blockIdx.x * 64;
    int tid = threadIdx.x;
    int ty = tid >> 4, tx = tid & 15;

    #pragma unroll
    for (int p = 0; p < 8; p++) {
        int idx = tid + p * 256;
        int row = idx >> 5, d4 = idx & 31;
        qs[row * 32 + (d4 ^ (row >> 2))] =
            *(const float4*)&q[(((b * T_ + t0 + row) * H_ + h) << 7) + d4 * 4];
    }

    float m[4], l[4], acc[4][8];
    #pragma unroll
    for (int i = 0; i < 4; i++) {
        m[i] = -1e30f; l[i] = 0.f;
        #pragma unroll
        for (int j = 0; j < 8; j++) acc[i][j] = 0.f;
    }

    for (int kt = 0; kt < T_ / 64; kt++) {
        __syncthreads();
        #pragma unroll
        for (int p = 0; p < 8; p++) {
            int idx = tid + p * 256;
            int row = idx >> 5, d4 = idx & 31;
            kvs[row * 32 + (d4 ^ (row >> 2))] =
                *(const float4*)&k[(((b * T_ + kt * 64 + row) * KV_ + kvh) << 7) + d4 * 4];
        }
        __syncthreads();

        float s[4][4] = {};
        #pragma unroll 4
        for (int d4 = 0; d4 < 32; d4++) {
            float4 qv[4], kv[4];
            #pragma unroll
            for (int i = 0; i < 4; i++) qv[i] = qs[(ty * 4 + i) * 32 + (d4 ^ ty)];
            #pragma unroll
            for (int j = 0; j < 4; j++) kv[j] = kvs[(tx * 4 + j) * 32 + (d4 ^ tx)];
            #pragma unroll
            for (int i = 0; i < 4; i++)
                #pragma unroll
                for (int j = 0; j < 4; j++)
                    s[i][j] += qv[i].x * kv[j].x + qv[i].y * kv[j].y
                             + qv[i].z * kv[j].z + qv[i].w * kv[j].w;
        }

        #pragma unroll
        for (int i = 0; i < 4; i++) {
            float rm = fmaxf(fmaxf(s[i][0], s[i][1]), fmaxf(s[i][2], s[i][3]));
            #pragma unroll
            for (int off = 8; off; off >>= 1)
                rm = fmaxf(rm, __shfl_xor_sync(0xffffffffu, rm, off, 16));
            float nm = fmaxf(m[i], rm);
            float pj[4], rs = 0.f;
            #pragma unroll
            for (int j = 0; j < 4; j++) { pj[j] = __expf(s[i][j] - nm); rs += pj[j]; }
            #pragma unroll
            for (int off = 8; off; off >>= 1)
                rs += __shfl_xor_sync(0xffffffffu, rs, off, 16);
            float corr = __expf(m[i] - nm);
            l[i] = l[i] * corr + rs;
            m[i] = nm;
            #pragma unroll
            for (int j = 0; j < 8; j++) acc[i][j] *= corr;
            *(float4*)&ps[(ty * 4 + i) * 64 + tx * 4] = make_float4(pj[0], pj[1], pj[2], pj[3]);
        }
        __syncthreads();

        #pragma unroll
        for (int p = 0; p < 8; p++) {
            int idx = tid + p * 256;
            int row = idx >> 5, d4 = idx & 31;
            kvs[row * 32 + (d4 ^ (row >> 2))] =
                *(const float4*)&v[(((b * T_ + kt * 64 + row) * KV_ + kvh) << 7) + d4 * 4];
        }
        __syncthreads();

        #pragma unroll 2
        for (int kk = 0; kk < 64; kk++) {
            float4 va = kvs[kk * 32 + ((tx * 2)     ^ (kk >> 2))];
            float4 vb = kvs[kk * 32 + ((tx * 2 + 1) ^ (kk >> 2))];
            #pragma unroll
            for (int i = 0; i < 4; i++) {
                float pv = ps[(ty * 4 + i) * 64 + kk];
                acc[i][0] += pv * va.x; acc[i][1] += pv * va.y;
                acc[i][2] += pv * va.z; acc[i][3] += pv * va.w;
                acc[i][4] += pv * vb.x; acc[i][5] += pv * vb.y;
                acc[i][6] += pv * vb.z; acc[i][7] += pv * vb.w;
            }
        }
    }

    #pragma unroll
    for (int i = 0; i < 4; i++) {
        float inv = 1.0f / l[i];
        float* op = &o[(((b * T_ + t0 + ty * 4 + i) * H_ + h) << 7) + tx * 8];
        *(float4*)op       = make_float4(acc[i][0] * inv, acc[i][1] * inv,
                                         acc[i][2] * inv, acc[i][3] * inv);
        *(float4*)(op + 4) = make_float4(acc[i][4] * inv, acc[i][5] * inv,
                                         acc[i][6] * inv, acc[i][7] * inv);
    }
}

// ---------------------------------------------------------------------------
// Launch: QKV GEMMs (tf32 MMA) -> RMSNorm+RoPE -> flash attn -> Wo GEMM
// ---------------------------------------------------------------------------
extern "C" void kernel_launch(void* const* d_in, const int* in_sizes, int n_in,
                              void* d_out, int out_size)
{
    const float* x    = (const float*)d_in[0];
    const float* cosT = (const float*)d_in[1];
    const float* sinT = (const float*)d_in[2];
    const float* Wq   = (const float*)d_in[3];
    const float* Wk   = (const float*)d_in[4];
    const float* Wv   = (const float*)d_in[5];
    const float* Wo   = (const float*)d_in[6];
    const float* qg   = (const float*)d_in[7];
    const float* kg   = (const float*)d_in[8];

    float *q, *k, *v, *o;
    cudaGetSymbolAddress((void**)&q, g_q);
    cudaGetSymbolAddress((void**)&k, g_k);
    cudaGetSymbolAddress((void**)&v, g_v);
    cudaGetSymbolAddress((void**)&o, g_o);

    const int M = B_ * T_;  // 8192

    gemm_tf32<<<dim3((H_ * HD_) / 128, M / 128), 256>>>(x, Wq, q, M, H_ * HD_, DM_);
    gemm_tf32<<<dim3((KV_ * HD_) / 128, M / 128), 256>>>(x, Wk, k, M, KV_ * HD_, DM_);
    gemm_tf32<<<dim3((KV_ * HD_) / 128, M / 128), 256>>>(x, Wv, v, M, KV_ * HD_, DM_);

    rmsrope<<<(M * H_) / 8, 256>>>(q, qg, cosT, sinT, H_, 0.0883883476483184405f);
    rmsrope<<<(M * KV_) / 8, 256>>>(k, kg, cosT, sinT, KV_, 1.0f);

    cudaFuncSetAttribute(attn64, cudaFuncAttributeMaxDynamicSharedMemorySize, 81920);
    attn64<<<dim3(T_ / 64, H_, B_), 256, 81920>>>(q, k, v, o);

    gemm_tf32<<<dim3(DM_ / 128, M / 128), 256>>>(o, Wo, (float*)d_out, M, DM_, DM_);
}

// round 3
// speedup vs baseline: 3.3598x; 3.3518x over previous
#include <cuda_runtime.h>
#include <math.h>
#include <stdint.h>

#define B_ 4
#define T_ 2048
#define DM_ 2048
#define H_ 16
#define KV_ 8
#define HD_ 128
#define G_ 2

// Scratch (no allocations allowed) — static device globals.
__device__ float g_q[B_*T_*H_*HD_];   // 64 MB
__device__ float g_k[B_*T_*KV_*HD_];  // 32 MB
__device__ float g_v[B_*T_*KV_*HD_];  // 32 MB
__device__ float g_o[B_*T_*H_*HD_];   // 64 MB

// ---------------------------------------------------------------------------
// TF32 helpers
// ---------------------------------------------------------------------------
__device__ __forceinline__ uint32_t f2tf32(float f) {
    uint32_t r;
    asm("cvt.rna.tf32.f32 %0, %1;" : "=r"(r) : "f"(f));
    return r;
}

__device__ __forceinline__ void mma_tf32(float c[4],
                                         uint32_t a0, uint32_t a1, uint32_t a2, uint32_t a3,
                                         uint32_t b0, uint32_t b1) {
    asm volatile(
        "mma.sync.aligned.m16n8k8.row.col.f32.tf32.tf32.f32 "
        "{%0,%1,%2,%3}, {%4,%5,%6,%7}, {%8,%9}, {%0,%1,%2,%3};"
        : "+f"(c[0]), "+f"(c[1]), "+f"(c[2]), "+f"(c[3])
        : "r"(a0), "r"(a1), "r"(a2), "r"(a3), "r"(b0), "r"(b1));
}

// ---------------------------------------------------------------------------
// TF32 tensor-core GEMM: C[M,N] = A[M,K] * W[K,N]. (unchanged from R1)
// ---------------------------------------------------------------------------
#define AS_STRIDE 36
#define BS_STRIDE 136

__global__ __launch_bounds__(256, 2)
void gemm_tf32(const float* __restrict__ A, const float* __restrict__ W,
               float* __restrict__ C, int M, int N, int K)
{
    __shared__ uint32_t As[128 * AS_STRIDE];
    __shared__ uint32_t Bs[32 * BS_STRIDE];

    int tid  = threadIdx.x;
    int lane = tid & 31;
    int warp = tid >> 5;
    int wm = (warp & 1) * 64;
    int wn = (warp >> 1) * 32;
    int bm = blockIdx.y * 128, bn = blockIdx.x * 128;

    float acc[4][4][4] = {};

    for (int k0 = 0; k0 < K; k0 += 32) {
        #pragma unroll
        for (int p = 0; p < 4; p++) {
            int idx = tid + p * 256;
            int m = idx >> 3, kk = (idx & 7) << 2;
            float4 a = *(const float4*)&A[(size_t)(bm + m) * K + k0 + kk];
            uint32_t* dst = &As[m * AS_STRIDE + kk];
            dst[0] = f2tf32(a.x); dst[1] = f2tf32(a.y);
            dst[2] = f2tf32(a.z); dst[3] = f2tf32(a.w);
        }
        #pragma unroll
        for (int p = 0; p < 4; p++) {
            int idx = tid + p * 256;
            int kk = idx >> 5, n = (idx & 31) << 2;
            float4 b = *(const float4*)&W[(size_t)(k0 + kk) * N + bn + n];
            uint32_t* dst = &Bs[kk * BS_STRIDE + n];
            dst[0] = f2tf32(b.x); dst[1] = f2tf32(b.y);
            dst[2] = f2tf32(b.z); dst[3] = f2tf32(b.w);
        }
        __syncthreads();

        #pragma unroll
        for (int ks = 0; ks < 4; ks++) {
            int kc = ks * 8 + (lane & 3);
            uint32_t af[4][4];
            #pragma unroll
            for (int fm = 0; fm < 4; fm++) {
                int r = wm + fm * 16 + (lane >> 2);
                af[fm][0] = As[r * AS_STRIDE + kc];
                af[fm][1] = As[(r + 8) * AS_STRIDE + kc];
                af[fm][2] = As[r * AS_STRIDE + kc + 4];
                af[fm][3] = As[(r + 8) * AS_STRIDE + kc + 4];
            }
            #pragma unroll
            for (int fn = 0; fn < 4; fn++) {
                int n = wn + fn * 8 + (lane >> 2);
                uint32_t b0 = Bs[kc * BS_STRIDE + n];
                uint32_t b1 = Bs[(kc + 4) * BS_STRIDE + n];
                #pragma unroll
                for (int fm = 0; fm < 4; fm++)
                    mma_tf32(acc[fm][fn], af[fm][0], af[fm][1], af[fm][2], af[fm][3], b0, b1);
            }
        }
        __syncthreads();
    }

    #pragma unroll
    for (int fm = 0; fm < 4; fm++) {
        #pragma unroll
        for (int fn = 0; fn < 4; fn++) {
            int r = bm + wm + fm * 16 + (lane >> 2);
            int c = bn + wn + fn * 8 + (lane & 3) * 2;
            *(float2*)&C[(size_t)r * N + c]       = make_float2(acc[fm][fn][0], acc[fm][fn][1]);
            *(float2*)&C[(size_t)(r + 8) * N + c] = make_float2(acc[fm][fn][2], acc[fm][fn][3]);
        }
    }
}

// ---------------------------------------------------------------------------
// Fused RMSNorm + interleaved RoPE (1/sqrt(HD) folded into q). (unchanged)
// ---------------------------------------------------------------------------
__global__ void rmsrope(float* __restrict__ buf, const float* __restrict__ gamma,
                        const float* __restrict__ cosT, const float* __restrict__ sinT,
                        int nheads, float outscale)
{
    int gid  = blockIdx.x * blockDim.x + threadIdx.x;
    int lane = gid & 31;
    int w    = gid >> 5;
    int t    = (w / nheads) % T_;
    float* p = buf + (size_t)w * HD_ + lane * 4;
    float4 v = *(float4*)p;
    float ss = v.x * v.x + v.y * v.y + v.z * v.z + v.w * v.w;
    #pragma unroll
    for (int off = 16; off; off >>= 1) ss += __shfl_xor_sync(0xffffffffu, ss, off);
    float r = rsqrtf(ss * (1.0f / HD_) + 1e-6f);
    float4 g = *(const float4*)&gamma[lane * 4];
    float hx = v.x * r * g.x, hy = v.y * r * g.y;
    float hz = v.z * r * g.z, hw = v.w * r * g.w;
    int ci = t * HD_ + lane * 4;
    float c0 = cosT[ci], s0 = sinT[ci], c1 = cosT[ci + 2], s1 = sinT[ci + 2];
    float4 o;
    o.x = (hx * c0 - hy * s0) * outscale;
    o.y = (hy * c0 + hx * s0) * outscale;
    o.z = (hz * c1 - hw * s1) * outscale;
    o.w = (hw * c1 + hz * s1) * outscale;
    *(float4*)p = o;
}

// ---------------------------------------------------------------------------
// Tensor-core flash attention (non-causal). 128 q-rows/CTA, 8 warps (16 rows
// each), 64-wide K/V tiles, tf32 m16n8k8 MMA for both QK^T and PV.
// Smem strides chosen for conflict-free fragment LDS:
//   qs,ks stride 132 (A-style access, row=lane/4):  banks 4*(l/4)+l%4
//   vs    stride 136 (B-style access, row=lane%4):  banks 8*(l%4)+l/4
//   ps    stride  68 (A-style)
// ---------------------------------------------------------------------------
#define QS_ST 132
#define KS_ST 132
#define VS_ST 136
#define PS_ST 68
#define ATTN_SMEM ((128*QS_ST + 64*KS_ST + 64*VS_ST + 128*PS_ST) * 4)

__global__ __launch_bounds__(256, 1)
void attn_mma(const float* __restrict__ q, const float* __restrict__ k,
              const float* __restrict__ v, float* __restrict__ o)
{
    extern __shared__ uint32_t sm[];
    uint32_t* qs = sm;                    // 128 x 132
    uint32_t* ks = qs + 128 * QS_ST;      // 64 x 132
    uint32_t* vs = ks + 64 * KS_ST;       // 64 x 136
    uint32_t* ps = vs + 64 * VS_ST;       // 128 x 68 (tf32 bits of P)

    int b = blockIdx.z, h = blockIdx.y;
    int kvh = h / G_;
    int t0 = blockIdx.x * 128;
    int tid = threadIdx.x, lane = tid & 31, warp = tid >> 5;
    int qr = lane >> 2;                   // quad row 0..7
    int ql = lane & 3;                    // quad lane 0..3

    // Stage Q tile (128 x 128) once, converted to tf32.
    #pragma unroll
    for (int p = 0; p < 16; p++) {
        int idx = tid + p * 256;
        int row = idx >> 5, c4 = (idx & 31) << 2;
        float4 a = *(const float4*)&q[(((size_t)(b * T_ + t0 + row) * H_ + h) << 7) + c4];
        uint32_t* d = &qs[row * QS_ST + c4];
        d[0] = f2tf32(a.x); d[1] = f2tf32(a.y); d[2] = f2tf32(a.z); d[3] = f2tf32(a.w);
    }

    float m1 = -1e30f, m2 = -1e30f, l1 = 0.f, l2 = 0.f;
    float oa[16][4] = {};                 // O accum: [hd-frag][c-reg]
    int r1 = warp * 16 + qr;              // this thread's first q-row (in tile)

    for (int kt = 0; kt < T_ / 64; kt++) {
        __syncthreads();  // prev iter done reading ks/vs
        // Stage K and V tiles (64 x 128 each) as tf32.
        #pragma unroll
        for (int p = 0; p < 8; p++) {
            int idx = tid + p * 256;
            int row = idx >> 5, c4 = (idx & 31) << 2;
            size_t gofs = (((size_t)(b * T_ + kt * 64 + row) * KV_ + kvh) << 7) + c4;
            float4 kk = *(const float4*)&k[gofs];
            uint32_t* dk = &ks[row * KS_ST + c4];
            dk[0] = f2tf32(kk.x); dk[1] = f2tf32(kk.y);
            dk[2] = f2tf32(kk.z); dk[3] = f2tf32(kk.w);
            float4 vv = *(const float4*)&v[gofs];
            uint32_t* dv = &vs[row * VS_ST + c4];
            dv[0] = f2tf32(vv.x); dv[1] = f2tf32(vv.y);
            dv[2] = f2tf32(vv.z); dv[3] = f2tf32(vv.w);
        }
        __syncthreads();

        // S = Q @ K^T  (16 rows x 64 cols per warp); k-dim = HD = 16 steps.
        float s[8][4] = {};
        #pragma unroll
        for (int kc8 = 0; kc8 < 128; kc8 += 8) {
            int kc = kc8 + ql;
            uint32_t a0 = qs[r1 * QS_ST + kc];
            uint32_t a1 = qs[(r1 + 8) * QS_ST + kc];
            uint32_t a2 = qs[r1 * QS_ST + kc + 4];
            uint32_t a3 = qs[(r1 + 8) * QS_ST + kc + 4];
            #pragma unroll
            for (int nf = 0; nf < 8; nf++) {
                int n = nf * 8 + qr;
                uint32_t b0 = ks[n * KS_ST + kc];
                uint32_t b1 = ks[n * KS_ST + kc + 4];
                mma_tf32(s[nf], a0, a1, a2, a3, b0, b1);
            }
        }

        // Online softmax. Thread owns rows r1 (c0,c1) and r1+8 (c2,c3);
        // row group = the 4 lanes sharing lane>>2.
        float rm1 = -1e30f, rm2 = -1e30f;
        #pragma unroll
        for (int nf = 0; nf < 8; nf++) {
            rm1 = fmaxf(rm1, fmaxf(s[nf][0], s[nf][1]));
            rm2 = fmaxf(rm2, fmaxf(s[nf][2], s[nf][3]));
        }
        #pragma unroll
        for (int off = 1; off <= 2; off <<= 1) {
            rm1 = fmaxf(rm1, __shfl_xor_sync(0xffffffffu, rm1, off));
            rm2 = fmaxf(rm2, __shfl_xor_sync(0xffffffffu, rm2, off));
        }
        float nm1 = fmaxf(m1, rm1), nm2 = fmaxf(m2, rm2);
        float rs1 = 0.f, rs2 = 0.f;
        #pragma unroll
        for (int nf = 0; nf < 8; nf++) {
            float p0 = __expf(s[nf][0] - nm1);
            float p1 = __expf(s[nf][1] - nm1);
            float p2 = __expf(s[nf][2] - nm2);
            float p3 = __expf(s[nf][3] - nm2);
            rs1 += p0 + p1; rs2 += p2 + p3;
            int c = nf * 8 + ql * 2;
            ps[r1 * PS_ST + c]           = f2tf32(p0);
            ps[r1 * PS_ST + c + 1]       = f2tf32(p1);
            ps[(r1 + 8) * PS_ST + c]     = f2tf32(p2);
            ps[(r1 + 8) * PS_ST + c + 1] = f2tf32(p3);
        }
        #pragma unroll
        for (int off = 1; off <= 2; off <<= 1) {
            rs1 += __shfl_xor_sync(0xffffffffu, rs1, off);
            rs2 += __shfl_xor_sync(0xffffffffu, rs2, off);
        }
        float corr1 = __expf(m1 - nm1), corr2 = __expf(m2 - nm2);
        l1 = l1 * corr1 + rs1; m1 = nm1;
        l2 = l2 * corr2 + rs2; m2 = nm2;
        #pragma unroll
        for (int nf = 0; nf < 16; nf++) {
            oa[nf][0] *= corr1; oa[nf][1] *= corr1;
            oa[nf][2] *= corr2; oa[nf][3] *= corr2;
        }
        __syncwarp();  // P stripe is warp-private: warp-level ordering suffices

        // O += P @ V  (16 rows x 128 hd per warp); k-dim = 64 seq = 8 steps.
        #pragma unroll
        for (int kc8 = 0; kc8 < 64; kc8 += 8) {
            int kc = kc8 + ql;
            uint32_t a0 = ps[r1 * PS_ST + kc];
            uint32_t a1 = ps[(r1 + 8) * PS_ST + kc];
            uint32_t a2 = ps[r1 * PS_ST + kc + 4];
            uint32_t a3 = ps[(r1 + 8) * PS_ST + kc + 4];
            #pragma unroll
            for (int nf = 0; nf < 16; nf++) {
                int n = nf * 8 + qr;
                uint32_t b0 = vs[kc * VS_ST + n];
                uint32_t b1 = vs[(kc + 4) * VS_ST + n];
                mma_tf32(oa[nf], a0, a1, a2, a3, b0, b1);
            }
        }
    }

    // Epilogue: normalize by l and store.
    float inv1 = 1.0f / l1, inv2 = 1.0f / l2;
    size_t base1 = ((size_t)(b * T_ + t0 + r1) * H_ + h) << 7;
    size_t base2 = ((size_t)(b * T_ + t0 + r1 + 8) * H_ + h) << 7;
    #pragma unroll
    for (int nf = 0; nf < 16; nf++) {
        int c = nf * 8 + ql * 2;
        *(float2*)&o[base1 + c] = make_float2(oa[nf][0] * inv1, oa[nf][1] * inv1);
        *(float2*)&o[base2 + c] = make_float2(oa[nf][2] * inv2, oa[nf][3] * inv2);
    }
}

// ---------------------------------------------------------------------------
// Launch
// ---------------------------------------------------------------------------
extern "C" void kernel_launch(void* const* d_in, const int* in_sizes, int n_in,
                              void* d_out, int out_size)
{
    const float* x    = (const float*)d_in[0];
    const float* cosT = (const float*)d_in[1];
    const float* sinT = (const float*)d_in[2];
    const float* Wq   = (const float*)d_in[3];
    const float* Wk   = (const float*)d_in[4];
    const float* Wv   = (const float*)d_in[5];
    const float* Wo   = (const float*)d_in[6];
    const float* qg   = (const float*)d_in[7];
    const float* kg   = (const float*)d_in[8];

    float *q, *k, *v, *o;
    cudaGetSymbolAddress((void**)&q, g_q);
    cudaGetSymbolAddress((void**)&k, g_k);
    cudaGetSymbolAddress((void**)&v, g_v);
    cudaGetSymbolAddress((void**)&o, g_o);

    const int M = B_ * T_;  // 8192

    gemm_tf32<<<dim3((H_ * HD_) / 128, M / 128), 256>>>(x, Wq, q, M, H_ * HD_, DM_);
    gemm_tf32<<<dim3((KV_ * HD_) / 128, M / 128), 256>>>(x, Wk, k, M, KV_ * HD_, DM_);
    gemm_tf32<<<dim3((KV_ * HD_) / 128, M / 128), 256>>>(x, Wv, v, M, KV_ * HD_, DM_);

    rmsrope<<<(M * H_) / 8, 256>>>(q, qg, cosT, sinT, H_, 0.0883883476483184405f);
    rmsrope<<<(M * KV_) / 8, 256>>>(k, kg, cosT, sinT, KV_, 1.0f);

    cudaFuncSetAttribute(attn_mma, cudaFuncAttributeMaxDynamicSharedMemorySize, ATTN_SMEM);
    attn_mma<<<dim3(T_ / 128, H_, B_), 256, ATTN_SMEM>>>(q, k, v, o);

    gemm_tf32<<<dim3(DM_ / 128, M / 128), 256>>>(o, Wo, (float*)d_out, M, DM_, DM_);
}